// round 6
// baseline (speedup 1.0000x reference)
#include <cuda_runtime.h>
#include <math.h>

// Problem constants
#define L_  4096
#define H_  512
#define P_  256
#define B_  8
#define PC  512                 // 2*P (re plane then im plane)
#define ML  (B_ * L_)           // 32768

// GEMM tiling
#define BM  128
#define BN  128
#define BK  16
#define PADW 132                // row stride (floats) for smem tiles; 132*4=528 is 16B-aligned

// Scratch: Bu / xs buffer in (b, pc, l) layout, scanned in place. 67 MB.
__device__ float g_buf[(size_t)B_ * PC * L_];
__device__ float g_W1t[(size_t)H_ * PC];   // (h, pc): W1t[h*PC + pc]
__device__ float g_W2 [(size_t)PC * H_];   // (pc, h): W2[pc*H + h]
__device__ float g_lamre[P_], g_lamim[P_];

// ---------------------------------------------------------------------------
// K0: discretize + build fused weight matrices
// ---------------------------------------------------------------------------
__global__ void prep_kernel(const float* __restrict__ lre, const float* __restrict__ lim,
                            const float* __restrict__ Bre, const float* __restrict__ Bim,
                            const float* __restrict__ Cre, const float* __restrict__ Cim,
                            const float* __restrict__ logdt)
{
    int pc = blockIdx.x;            // 0..511
    int h  = threadIdx.x;           // 0..511
    int p  = pc & (P_ - 1);
    bool isim = pc >= P_;

    float lr = lre[p], li = lim[p];
    float dt = expf(logdt[p]);
    // lambda_bar = exp((lr + i*li) * dt)
    float e   = expf(lr * dt);
    float lbr = e * cosf(li * dt);
    float lbi = e * sinf(li * dt);
    // g = (lambda_bar - 1) / lambda
    float ar = lbr - 1.0f, ai = lbi;
    float den = lr * lr + li * li;
    float gr = (ar * lr + ai * li) / den;
    float gi = (ai * lr - ar * li) / den;
    // B_bar = g * (B_re + i*B_im)
    float br = Bre[p * H_ + h], bi = Bim[p * H_ + h];
    g_W1t[(size_t)h * PC + pc] = isim ? (gr * bi + gi * br) : (gr * br - gi * bi);
    // Output projection: y = 2*(xr @ C_re^T - xi @ C_im^T)
    g_W2[(size_t)pc * H_ + h]  = isim ? (-2.0f * Cim[h * P_ + p]) : (2.0f * Cre[h * P_ + p]);

    if (h == 0 && !isim) { g_lamre[p] = lbr; g_lamim[p] = lbi; }
}

// ---------------------------------------------------------------------------
// K1: Bu[pc, m] = sum_h W1t[h, pc] * u[m, h]     (out in (b, pc, l) layout)
//   A = W1t  (k-major, pc contiguous)  -> direct smem copy
//   B = u    (k contiguous)            -> smem transpose
//   Double-buffered smem; register prefetch of next tile overlaps FFMA block.
//   Grid: x = pc tiles (4), y = m tiles (256) -> 4 consecutive bids share a
//   u tile (L2 reuse).
// ---------------------------------------------------------------------------
__global__ __launch_bounds__(256, 2)
void gemm1_kernel(const float* __restrict__ u)
{
    __shared__ float As[2][BK][PADW];   // [buf][k][pc]
    __shared__ float Bs[2][BK][PADW];   // [buf][k][m]

    int r0 = blockIdx.x * BM;        // pc tile
    int c0 = blockIdx.y * BN;        // m tile (stays within one batch b)
    int t  = threadIdx.x;
    int tx = t & 15, ty = t >> 4;

    // per-thread load coordinates (2 float4 each for A and B)
    int a_kk[2], a_rr[2], b_cc[2], b_kb[2];
#pragma unroll
    for (int i = 0; i < 2; i++) {
        int f = t + i * 256;
        a_kk[i] = f >> 5;  a_rr[i] = (f & 31) << 2;
        b_cc[i] = f >> 2;  b_kb[i] = (f & 3) << 2;
    }

    float acc[8][8];
#pragma unroll
    for (int i = 0; i < 8; i++)
#pragma unroll
        for (int j = 0; j < 8; j++) acc[i][j] = 0.0f;

    // prologue: tile 0 -> buffer 0
#pragma unroll
    for (int i = 0; i < 2; i++) {
        float4 v = *(const float4*)(g_W1t + (size_t)a_kk[i] * PC + r0 + a_rr[i]);
        *(float4*)&As[0][a_kk[i]][a_rr[i]] = v;
        float4 w = *(const float4*)(u + (size_t)(c0 + b_cc[i]) * H_ + b_kb[i]);
        Bs[0][b_kb[i] + 0][b_cc[i]] = w.x;
        Bs[0][b_kb[i] + 1][b_cc[i]] = w.y;
        Bs[0][b_kb[i] + 2][b_cc[i]] = w.z;
        Bs[0][b_kb[i] + 3][b_cc[i]] = w.w;
    }
    __syncthreads();

    const int NT = H_ / BK;          // 32
    for (int tI = 0; tI < NT; tI++) {
        int cur = tI & 1;
        bool has_next = (tI + 1 < NT);
        int k1 = (tI + 1) * BK;

        // issue next-tile global loads into registers (latency hidden by FFMAs)
        float4 ra[2], rb[2];
        if (has_next) {
#pragma unroll
            for (int i = 0; i < 2; i++) {
                ra[i] = *(const float4*)(g_W1t + (size_t)(k1 + a_kk[i]) * PC + r0 + a_rr[i]);
                rb[i] = *(const float4*)(u + (size_t)(c0 + b_cc[i]) * H_ + k1 + b_kb[i]);
            }
        }

#pragma unroll
        for (int kk = 0; kk < BK; kk++) {
            float a[8], b[8];
            *(float4*)(a)     = *(const float4*)&As[cur][kk][ty * 8];
            *(float4*)(a + 4) = *(const float4*)&As[cur][kk][ty * 8 + 4];
            *(float4*)(b)     = *(const float4*)&Bs[cur][kk][tx * 8];
            *(float4*)(b + 4) = *(const float4*)&Bs[cur][kk][tx * 8 + 4];
#pragma unroll
            for (int i = 0; i < 8; i++)
#pragma unroll
                for (int j = 0; j < 8; j++)
                    acc[i][j] = fmaf(a[i], b[j], acc[i][j]);
        }

        if (has_next) {
            int nxt = cur ^ 1;
#pragma unroll
            for (int i = 0; i < 2; i++) {
                *(float4*)&As[nxt][a_kk[i]][a_rr[i]] = ra[i];
                Bs[nxt][b_kb[i] + 0][b_cc[i]] = rb[i].x;
                Bs[nxt][b_kb[i] + 1][b_cc[i]] = rb[i].y;
                Bs[nxt][b_kb[i] + 2][b_cc[i]] = rb[i].z;
                Bs[nxt][b_kb[i] + 3][b_cc[i]] = rb[i].w;
            }
        }
        __syncthreads();
    }

    // write: element (r, c=b*L+l) -> g_buf[b*PC*L + r*L + l]
    int b  = c0 >> 12;               // c0 / 4096
    int l0 = c0 & (L_ - 1);
    size_t base = (size_t)b * PC * L_;
#pragma unroll
    for (int i = 0; i < 8; i++) {
        size_t row = base + (size_t)(r0 + ty * 8 + i) * L_ + l0 + tx * 8;
        float4 v0 = make_float4(acc[i][0], acc[i][1], acc[i][2], acc[i][3]);
        float4 v1 = make_float4(acc[i][4], acc[i][5], acc[i][6], acc[i][7]);
        *(float4*)(g_buf + row)     = v0;
        *(float4*)(g_buf + row + 4) = v1;
    }
}

// ---------------------------------------------------------------------------
// K2: in-place scan along l for each (b, p):  x_k = lambda*x_{k-1} + Bu_k
//   128 threads, 32-element serial chunk each, Kogge-Stone carry combine.
// ---------------------------------------------------------------------------
__global__ __launch_bounds__(128)
void scan_kernel()
{
    int p = blockIdx.x;
    int b = blockIdx.y;
    float* re = g_buf + (size_t)b * PC * L_ + (size_t)p * L_;
    float* im = re + (size_t)P_ * L_;

    float lr = g_lamre[p], li = g_lamim[p];
    int t = threadIdx.x;

    float xr[32], xi[32];
    const float4* r4 = (const float4*)(re + t * 32);
    const float4* i4 = (const float4*)(im + t * 32);
#pragma unroll
    for (int i = 0; i < 8; i++) {
        float4 v = r4[i];
        xr[i * 4 + 0] = v.x; xr[i * 4 + 1] = v.y; xr[i * 4 + 2] = v.z; xr[i * 4 + 3] = v.w;
        float4 w = i4[i];
        xi[i * 4 + 0] = w.x; xi[i * 4 + 1] = w.y; xi[i * 4 + 2] = w.z; xi[i * 4 + 3] = w.w;
    }

    // serial local scan (x starts at 0 within chunk)
    float ar = 0.0f, ai = 0.0f;
#pragma unroll
    for (int j = 0; j < 32; j++) {
        float nr = fmaf(lr, ar, fmaf(-li, ai, xr[j]));
        float ni = fmaf(lr, ai, fmaf( li, ar, xi[j]));
        ar = nr; ai = ni;
        xr[j] = ar; xi[j] = ai;
    }

    __shared__ float sr[128], si[128];
    sr[t] = ar; si[t] = ai;

    // lambda^32 by 5 squarings
    float wr = lr, wi = li;
#pragma unroll
    for (int q = 0; q < 5; q++) { float nr = wr * wr - wi * wi; wi = 2.0f * wr * wi; wr = nr; }

    __syncthreads();
    // inclusive scan of carries: I_t += lam32^d * I_{t-d}
    for (int d = 1; d < 128; d <<= 1) {
        float vr = 0.0f, vi = 0.0f;
        bool act = (t >= d);
        if (act) { vr = sr[t - d]; vi = si[t - d]; }
        __syncthreads();
        if (act) {
            float nr = fmaf(wr, vr, fmaf(-wi, vi, sr[t]));
            float ni = fmaf(wr, vi, fmaf( wi, vr, si[t]));
            sr[t] = nr; si[t] = ni;
        }
        __syncthreads();
        float nr = wr * wr - wi * wi; wi = 2.0f * wr * wi; wr = nr;
    }

    // exclusive prefix = state entering this chunk
    float Er = 0.0f, Ei = 0.0f;
    if (t > 0) { Er = sr[t - 1]; Ei = si[t - 1]; }

    // fixup: x_j += lambda^{j+1} * E
    float pr = lr, pi = li;
#pragma unroll
    for (int j = 0; j < 32; j++) {
        xr[j] = fmaf(pr, Er, fmaf(-pi, Ei, xr[j]));
        xi[j] = fmaf(pr, Ei, fmaf( pi, Er, xi[j]));
        float nr = pr * lr - pi * li;
        pi = pr * li + pi * lr;
        pr = nr;
    }

    float4* wr4 = (float4*)(re + t * 32);
    float4* wi4 = (float4*)(im + t * 32);
#pragma unroll
    for (int i = 0; i < 8; i++) {
        wr4[i] = make_float4(xr[i * 4 + 0], xr[i * 4 + 1], xr[i * 4 + 2], xr[i * 4 + 3]);
        wi4[i] = make_float4(xi[i * 4 + 0], xi[i * 4 + 1], xi[i * 4 + 2], xi[i * 4 + 3]);
    }
}

// ---------------------------------------------------------------------------
// K3: y[m, h] = sum_pc xs[pc, m] * W2[pc, h] + D[h]*u[m, h]
//   Both operands k-major -> direct smem copies, no transpose.
//   Double-buffered smem with register prefetch.
//   Grid: x = h tiles (4), y = m tiles (256) -> 4 consecutive bids share a
//   g_buf A-tile (L2 reuse).
// ---------------------------------------------------------------------------
__global__ __launch_bounds__(256, 2)
void gemm2_kernel(const float* __restrict__ u, const float* __restrict__ D,
                  float* __restrict__ y)
{
    __shared__ float As[2][BK][PADW];   // [buf][k][m]
    __shared__ float Bs[2][BK][PADW];   // [buf][k][h]

    int h0 = blockIdx.x * BN;
    int m0 = blockIdx.y * BM;
    int t  = threadIdx.x;
    int tx = t & 15, ty = t >> 4;

    int b  = m0 >> 12;
    int l0 = m0 & (L_ - 1);
    const float* Abase = g_buf + (size_t)b * PC * L_ + l0;

    int kk_[2], cc_[2];
#pragma unroll
    for (int i = 0; i < 2; i++) {
        int f = t + i * 256;
        kk_[i] = f >> 5;
        cc_[i] = (f & 31) << 2;
    }

    float acc[8][8];
#pragma unroll
    for (int i = 0; i < 8; i++)
#pragma unroll
        for (int j = 0; j < 8; j++) acc[i][j] = 0.0f;

    // prologue: tile 0 -> buffer 0
#pragma unroll
    for (int i = 0; i < 2; i++) {
        *(float4*)&As[0][kk_[i]][cc_[i]] =
            *(const float4*)(Abase + (size_t)kk_[i] * L_ + cc_[i]);
        *(float4*)&Bs[0][kk_[i]][cc_[i]] =
            *(const float4*)(g_W2 + (size_t)kk_[i] * H_ + h0 + cc_[i]);
    }
    __syncthreads();

    const int NT = PC / BK;          // 32
    for (int tI = 0; tI < NT; tI++) {
        int cur = tI & 1;
        bool has_next = (tI + 1 < NT);
        int k1 = (tI + 1) * BK;

        float4 ra[2], rb[2];
        if (has_next) {
#pragma unroll
            for (int i = 0; i < 2; i++) {
                ra[i] = *(const float4*)(Abase + (size_t)(k1 + kk_[i]) * L_ + cc_[i]);
                rb[i] = *(const float4*)(g_W2 + (size_t)(k1 + kk_[i]) * H_ + h0 + cc_[i]);
            }
        }

#pragma unroll
        for (int kk = 0; kk < BK; kk++) {
            float a[8], bfr[8];
            *(float4*)(a)       = *(const float4*)&As[cur][kk][ty * 8];
            *(float4*)(a + 4)   = *(const float4*)&As[cur][kk][ty * 8 + 4];
            *(float4*)(bfr)     = *(const float4*)&Bs[cur][kk][tx * 8];
            *(float4*)(bfr + 4) = *(const float4*)&Bs[cur][kk][tx * 8 + 4];
#pragma unroll
            for (int i = 0; i < 8; i++)
#pragma unroll
                for (int j = 0; j < 8; j++)
                    acc[i][j] = fmaf(a[i], bfr[j], acc[i][j]);
        }

        if (has_next) {
            int nxt = cur ^ 1;
#pragma unroll
            for (int i = 0; i < 2; i++) {
                *(float4*)&As[nxt][kk_[i]][cc_[i]] = ra[i];
                *(float4*)&Bs[nxt][kk_[i]][cc_[i]] = rb[i];
            }
        }
        __syncthreads();
    }

    // epilogue: + D[h] * u[m, h]
    float dv[8];
    *(float4*)(dv)     = *(const float4*)(D + h0 + tx * 8);
    *(float4*)(dv + 4) = *(const float4*)(D + h0 + tx * 8 + 4);
#pragma unroll
    for (int i = 0; i < 8; i++) {
        size_t row = (size_t)(m0 + ty * 8 + i) * H_ + h0 + tx * 8;
        float4 u0 = *(const float4*)(u + row);
        float4 u1 = *(const float4*)(u + row + 4);
        float4 o0, o1;
        o0.x = fmaf(dv[0], u0.x, acc[i][0]);
        o0.y = fmaf(dv[1], u0.y, acc[i][1]);
        o0.z = fmaf(dv[2], u0.z, acc[i][2]);
        o0.w = fmaf(dv[3], u0.w, acc[i][3]);
        o1.x = fmaf(dv[4], u1.x, acc[i][4]);
        o1.y = fmaf(dv[5], u1.y, acc[i][5]);
        o1.z = fmaf(dv[6], u1.z, acc[i][6]);
        o1.w = fmaf(dv[7], u1.w, acc[i][7]);
        *(float4*)(y + row)     = o0;
        *(float4*)(y + row + 4) = o1;
    }
}

// ---------------------------------------------------------------------------
extern "C" void kernel_launch(void* const* d_in, const int* in_sizes, int n_in,
                              void* d_out, int out_size)
{
    const float* u     = (const float*)d_in[0];
    const float* lre   = (const float*)d_in[1];
    const float* lim   = (const float*)d_in[2];
    const float* Bre   = (const float*)d_in[3];
    const float* Bim   = (const float*)d_in[4];
    const float* Cre   = (const float*)d_in[5];
    const float* Cim   = (const float*)d_in[6];
    const float* D     = (const float*)d_in[7];
    const float* logdt = (const float*)d_in[8];
    float* y = (float*)d_out;

    prep_kernel<<<PC, H_>>>(lre, lim, Bre, Bim, Cre, Cim, logdt);
    gemm1_kernel<<<dim3(PC / BM, ML / BN), 256>>>(u);
    scan_kernel<<<dim3(P_, B_), 128>>>();
    gemm2_kernel<<<dim3(H_ / BN, ML / BM), 256>>>(u, D, y);
}

// round 15
// speedup vs baseline: 2.2176x; 2.2176x over previous
#include <cuda_runtime.h>
#include <math.h>
#include <stdint.h>

// Problem constants
#define L_  4096
#define H_  512
#define P_  256
#define B_  8
#define PC  512                 // 2*P (re plane then im plane)
#define ML  (B_ * L_)           // 32768

// GEMM tiling (tensor-core version)
#define BM  128
#define BN  128
#define BK  16
#define KST 20                  // [m][k] layout: padded k stride, conflict-free frag LDS
#define MST 136                 // [k][m] layout: padded m stride, conflict-free frag LDS + STS

// Scratch: Bu / xs buffer in (b, pc, l) layout, scanned in place. 67 MB.
__device__ float g_buf[(size_t)B_ * PC * L_];
__device__ float g_W1 [(size_t)PC * H_];   // (pc, h) row-major
__device__ float g_W2t[(size_t)H_ * PC];   // (h, pc) row-major
__device__ float g_lamre[P_], g_lamim[P_];

__device__ __forceinline__ float f2tf(float f) {
    uint32_t u;
    asm("cvt.rna.tf32.f32 %0, %1;" : "=r"(u) : "f"(f));
    return __uint_as_float(u);
}

__device__ __forceinline__ void mma_tf32(float* c, const uint32_t* a,
                                         uint32_t b0, uint32_t b1) {
    asm volatile(
        "mma.sync.aligned.m16n8k8.row.col.f32.tf32.tf32.f32 "
        "{%0,%1,%2,%3}, {%4,%5,%6,%7}, {%8,%9}, {%0,%1,%2,%3};"
        : "+f"(c[0]), "+f"(c[1]), "+f"(c[2]), "+f"(c[3])
        : "r"(a[0]), "r"(a[1]), "r"(a[2]), "r"(a[3]), "r"(b0), "r"(b1));
}

// ---------------------------------------------------------------------------
// K0: discretize + build fused weight matrices
// ---------------------------------------------------------------------------
__global__ void prep_kernel(const float* __restrict__ lre, const float* __restrict__ lim,
                            const float* __restrict__ Bre, const float* __restrict__ Bim,
                            const float* __restrict__ Cre, const float* __restrict__ Cim,
                            const float* __restrict__ logdt)
{
    int pc = blockIdx.x;            // 0..511
    int h  = threadIdx.x;           // 0..511
    int p  = pc & (P_ - 1);
    bool isim = pc >= P_;

    float lr = lre[p], li = lim[p];
    float dt = expf(logdt[p]);
    float e   = expf(lr * dt);
    float lbr = e * cosf(li * dt);
    float lbi = e * sinf(li * dt);
    float ar = lbr - 1.0f, ai = lbi;
    float den = lr * lr + li * li;
    float gr = (ar * lr + ai * li) / den;
    float gi = (ai * lr - ar * li) / den;
    float br = Bre[p * H_ + h], bi = Bim[p * H_ + h];
    g_W1[(size_t)pc * H_ + h]  = isim ? (gr * bi + gi * br) : (gr * br - gi * bi);
    g_W2t[(size_t)h * PC + pc] = isim ? (-2.0f * Cim[h * P_ + p]) : (2.0f * Cre[h * P_ + p]);

    if (h == 0 && !isim) { g_lamre[p] = lbr; g_lamim[p] = lbi; }
}

// ---------------------------------------------------------------------------
// K1 (tf32 tensor): Bu[pc, m] = sum_h W1[pc, h] * u[m, h]
//   A = W1 (pc, h) row-major; B = u (m, h) row-major; both direct f4 copies
//   into [m][k] KST layout (stores along k: contiguous; frag LDS conflict-free).
//   Out in (b, pc, l) layout. Grid x = pc tiles -> L2 reuse of u tile.
// ---------------------------------------------------------------------------
__global__ __launch_bounds__(256, 2)
void gemm1_kernel(const float* __restrict__ u)
{
    __shared__ float As[2][BM][KST];   // [buf][pc][k]
    __shared__ float Bs[2][BN][KST];   // [buf][m][k]

    int r0 = blockIdx.x * BM;        // pc tile
    int c0 = blockIdx.y * BN;        // m tile (within one batch)
    int t  = threadIdx.x;
    int lane = t & 31, wid = t >> 5;
    int wm = (wid & 3) * 32, wn = (wid >> 2) * 64;
    int gr = lane >> 2, tg = lane & 3;

    int lrow = t >> 2;               // 0..63 (+64 via i)
    int lcol = (t & 3) * 4;

    const float* Ag = g_W1 + (size_t)r0 * H_;
    const float* Bg = u    + (size_t)c0 * H_;

    float c[2][8][4];
#pragma unroll
    for (int mi = 0; mi < 2; mi++)
#pragma unroll
        for (int ni = 0; ni < 8; ni++)
#pragma unroll
            for (int q = 0; q < 4; q++) c[mi][ni][q] = 0.0f;

    // prologue: tile 0 -> buffer 0 (cvt to tf32 at store)
#pragma unroll
    for (int i = 0; i < 2; i++) {
        int row = lrow + i * 64;
        float4 va = *(const float4*)(Ag + (size_t)row * H_ + lcol);
        As[0][row][lcol + 0] = f2tf(va.x); As[0][row][lcol + 1] = f2tf(va.y);
        As[0][row][lcol + 2] = f2tf(va.z); As[0][row][lcol + 3] = f2tf(va.w);
        float4 vb = *(const float4*)(Bg + (size_t)row * H_ + lcol);
        Bs[0][row][lcol + 0] = f2tf(vb.x); Bs[0][row][lcol + 1] = f2tf(vb.y);
        Bs[0][row][lcol + 2] = f2tf(vb.z); Bs[0][row][lcol + 3] = f2tf(vb.w);
    }
    __syncthreads();

    const int NT = H_ / BK;          // 32
    for (int tI = 0; tI < NT; tI++) {
        int cur = tI & 1;
        bool hn = (tI + 1 < NT);
        int k1 = (tI + 1) * BK;

        float4 ra[2], rb[2];
        if (hn) {
#pragma unroll
            for (int i = 0; i < 2; i++) {
                int row = lrow + i * 64;
                ra[i] = *(const float4*)(Ag + (size_t)row * H_ + k1 + lcol);
                rb[i] = *(const float4*)(Bg + (size_t)row * H_ + k1 + lcol);
            }
        }

#pragma unroll
        for (int ks = 0; ks < 2; ks++) {
            int kb = ks * 8;
            uint32_t a[2][4];
#pragma unroll
            for (int mi = 0; mi < 2; mi++) {
                int r = wm + mi * 16 + gr;
                a[mi][0] = __float_as_uint(As[cur][r    ][kb + tg]);
                a[mi][1] = __float_as_uint(As[cur][r + 8][kb + tg]);
                a[mi][2] = __float_as_uint(As[cur][r    ][kb + tg + 4]);
                a[mi][3] = __float_as_uint(As[cur][r + 8][kb + tg + 4]);
            }
#pragma unroll
            for (int ni = 0; ni < 8; ni++) {
                int bc = wn + ni * 8 + gr;
                uint32_t b0 = __float_as_uint(Bs[cur][bc][kb + tg]);
                uint32_t b1 = __float_as_uint(Bs[cur][bc][kb + tg + 4]);
                mma_tf32(c[0][ni], a[0], b0, b1);
                mma_tf32(c[1][ni], a[1], b0, b1);
            }
        }

        if (hn) {
            int nx = cur ^ 1;
#pragma unroll
            for (int i = 0; i < 2; i++) {
                int row = lrow + i * 64;
                As[nx][row][lcol + 0] = f2tf(ra[i].x); As[nx][row][lcol + 1] = f2tf(ra[i].y);
                As[nx][row][lcol + 2] = f2tf(ra[i].z); As[nx][row][lcol + 3] = f2tf(ra[i].w);
                Bs[nx][row][lcol + 0] = f2tf(rb[i].x); Bs[nx][row][lcol + 1] = f2tf(rb[i].y);
                Bs[nx][row][lcol + 2] = f2tf(rb[i].z); Bs[nx][row][lcol + 3] = f2tf(rb[i].w);
            }
        }
        __syncthreads();
    }

    // epilogue: C[pc, m] -> g_buf[b*PC*L + pc*L + l]
    int b  = c0 >> 12;
    int l0 = c0 & (L_ - 1);
    float* out = g_buf + (size_t)b * PC * L_;
#pragma unroll
    for (int mi = 0; mi < 2; mi++) {
#pragma unroll
        for (int ni = 0; ni < 8; ni++) {
            int rp = r0 + wm + mi * 16 + gr;
            int cm = l0 + wn + ni * 8 + 2 * tg;
            float2 v0 = make_float2(c[mi][ni][0], c[mi][ni][1]);
            float2 v1 = make_float2(c[mi][ni][2], c[mi][ni][3]);
            *(float2*)(out + (size_t)rp * L_ + cm)       = v0;
            *(float2*)(out + (size_t)(rp + 8) * L_ + cm) = v1;
        }
    }
}

// ---------------------------------------------------------------------------
// K2: in-place scan along l for each (b, p):  x_k = lambda*x_{k-1} + Bu_k
// ---------------------------------------------------------------------------
__global__ __launch_bounds__(128)
void scan_kernel()
{
    int p = blockIdx.x;
    int b = blockIdx.y;
    float* re = g_buf + (size_t)b * PC * L_ + (size_t)p * L_;
    float* im = re + (size_t)P_ * L_;

    float lr = g_lamre[p], li = g_lamim[p];
    int t = threadIdx.x;

    float xr[32], xi[32];
    const float4* r4 = (const float4*)(re + t * 32);
    const float4* i4 = (const float4*)(im + t * 32);
#pragma unroll
    for (int i = 0; i < 8; i++) {
        float4 v = r4[i];
        xr[i * 4 + 0] = v.x; xr[i * 4 + 1] = v.y; xr[i * 4 + 2] = v.z; xr[i * 4 + 3] = v.w;
        float4 w = i4[i];
        xi[i * 4 + 0] = w.x; xi[i * 4 + 1] = w.y; xi[i * 4 + 2] = w.z; xi[i * 4 + 3] = w.w;
    }

    float ar = 0.0f, ai = 0.0f;
#pragma unroll
    for (int j = 0; j < 32; j++) {
        float nr = fmaf(lr, ar, fmaf(-li, ai, xr[j]));
        float ni = fmaf(lr, ai, fmaf( li, ar, xi[j]));
        ar = nr; ai = ni;
        xr[j] = ar; xi[j] = ai;
    }

    __shared__ float sr[128], si[128];
    sr[t] = ar; si[t] = ai;

    float wr = lr, wi = li;
#pragma unroll
    for (int q = 0; q < 5; q++) { float nr = wr * wr - wi * wi; wi = 2.0f * wr * wi; wr = nr; }

    __syncthreads();
    for (int d = 1; d < 128; d <<= 1) {
        float vr = 0.0f, vi = 0.0f;
        bool act = (t >= d);
        if (act) { vr = sr[t - d]; vi = si[t - d]; }
        __syncthreads();
        if (act) {
            float nr = fmaf(wr, vr, fmaf(-wi, vi, sr[t]));
            float ni = fmaf(wr, vi, fmaf( wi, vr, si[t]));
            sr[t] = nr; si[t] = ni;
        }
        __syncthreads();
        float nr = wr * wr - wi * wi; wi = 2.0f * wr * wi; wr = nr;
    }

    float Er = 0.0f, Ei = 0.0f;
    if (t > 0) { Er = sr[t - 1]; Ei = si[t - 1]; }

    float pr = lr, pi = li;
#pragma unroll
    for (int j = 0; j < 32; j++) {
        xr[j] = fmaf(pr, Er, fmaf(-pi, Ei, xr[j]));
        xi[j] = fmaf(pr, Ei, fmaf( pi, Er, xi[j]));
        float nr = pr * lr - pi * li;
        pi = pr * li + pi * lr;
        pr = nr;
    }

    float4* wr4 = (float4*)(re + t * 32);
    float4* wi4 = (float4*)(im + t * 32);
#pragma unroll
    for (int i = 0; i < 8; i++) {
        wr4[i] = make_float4(xr[i * 4 + 0], xr[i * 4 + 1], xr[i * 4 + 2], xr[i * 4 + 3]);
        wi4[i] = make_float4(xi[i * 4 + 0], xi[i * 4 + 1], xi[i * 4 + 2], xi[i * 4 + 3]);
    }
}

// ---------------------------------------------------------------------------
// K3 (tf32 tensor): y[m, h] = sum_pc xs[pc, m] * W2[pc, h] + D[h]*u[m, h]
//   A tile stored [k][m] (MST=136): transpose STS is contiguous along m
//   (STS.128, conflict-free) and frag LDS banks = 8*tg+gr+d, all distinct.
//   B = W2t (h, pc) direct copy into [n][k] KST layout.
//   Grid x = h tiles -> 4 bids share the xs A tile in L2.
// ---------------------------------------------------------------------------
__global__ __launch_bounds__(256, 2)
void gemm2_kernel(const float* __restrict__ u, const float* __restrict__ D,
                  float* __restrict__ y)
{
    __shared__ float As[2][BK][MST];   // [buf][k=pc][m]
    __shared__ float Bs[2][BN][KST];   // [buf][h][k=pc]

    int h0 = blockIdx.x * BN;
    int m0 = blockIdx.y * BM;
    int t  = threadIdx.x;
    int lane = t & 31, wid = t >> 5;
    int wm = (wid & 3) * 32, wn = (wid >> 2) * 64;
    int gr = lane >> 2, tg = lane & 3;

    int b  = m0 >> 12;
    int l0 = m0 & (L_ - 1);
    const float* Ag = g_buf + (size_t)b * PC * L_ + l0;   // row = pc, col = m (contig)
    const float* Bg = g_W2t + (size_t)h0 * PC;

    int a_mc = (t & 31) * 4;          // m offset 0..124 (per-warp full row)
    int lrow = t >> 2;                // B: h row 0..63 (+64)
    int lcol = (t & 3) * 4;           // B: k offset

    float c[2][8][4];
#pragma unroll
    for (int mi = 0; mi < 2; mi++)
#pragma unroll
        for (int ni = 0; ni < 8; ni++)
#pragma unroll
            for (int q = 0; q < 4; q++) c[mi][ni][q] = 0.0f;

    // prologue
#pragma unroll
    for (int i = 0; i < 2; i++) {
        int kr = wid + i * 8;
        float4 va = *(const float4*)(Ag + (size_t)kr * L_ + a_mc);
        float4 ca = make_float4(f2tf(va.x), f2tf(va.y), f2tf(va.z), f2tf(va.w));
        *(float4*)&As[0][kr][a_mc] = ca;
        int row = lrow + i * 64;
        float4 vb = *(const float4*)(Bg + (size_t)row * PC + lcol);
        Bs[0][row][lcol + 0] = f2tf(vb.x); Bs[0][row][lcol + 1] = f2tf(vb.y);
        Bs[0][row][lcol + 2] = f2tf(vb.z); Bs[0][row][lcol + 3] = f2tf(vb.w);
    }
    __syncthreads();

    const int NT = PC / BK;          // 32
    for (int tI = 0; tI < NT; tI++) {
        int cur = tI & 1;
        bool hn = (tI + 1 < NT);
        int k1 = (tI + 1) * BK;

        float4 ra[2], rb[2];
        if (hn) {
#pragma unroll
            for (int i = 0; i < 2; i++) {
                int kr = wid + i * 8;
                ra[i] = *(const float4*)(Ag + (size_t)(k1 + kr) * L_ + a_mc);
                int row = lrow + i * 64;
                rb[i] = *(const float4*)(Bg + (size_t)row * PC + k1 + lcol);
            }
        }

#pragma unroll
        for (int ks = 0; ks < 2; ks++) {
            int kb = ks * 8;
            uint32_t a[2][4];
#pragma unroll
            for (int mi = 0; mi < 2; mi++) {
                int r = wm + mi * 16 + gr;
                a[mi][0] = __float_as_uint(As[cur][kb + tg    ][r]);
                a[mi][1] = __float_as_uint(As[cur][kb + tg    ][r + 8]);
                a[mi][2] = __float_as_uint(As[cur][kb + tg + 4][r]);
                a[mi][3] = __float_as_uint(As[cur][kb + tg + 4][r + 8]);
            }
#pragma unroll
            for (int ni = 0; ni < 8; ni++) {
                int bc = wn + ni * 8 + gr;
                uint32_t b0 = __float_as_uint(Bs[cur][bc][kb + tg]);
                uint32_t b1 = __float_as_uint(Bs[cur][bc][kb + tg + 4]);
                mma_tf32(c[0][ni], a[0], b0, b1);
                mma_tf32(c[1][ni], a[1], b0, b1);
            }
        }

        if (hn) {
            int nx = cur ^ 1;
#pragma unroll
            for (int i = 0; i < 2; i++) {
                int kr = wid + i * 8;
                float4 ca = make_float4(f2tf(ra[i].x), f2tf(ra[i].y),
                                        f2tf(ra[i].z), f2tf(ra[i].w));
                *(float4*)&As[nx][kr][a_mc] = ca;
                int row = lrow + i * 64;
                Bs[nx][row][lcol + 0] = f2tf(rb[i].x); Bs[nx][row][lcol + 1] = f2tf(rb[i].y);
                Bs[nx][row][lcol + 2] = f2tf(rb[i].z); Bs[nx][row][lcol + 3] = f2tf(rb[i].w);
            }
        }
        __syncthreads();
    }

    // epilogue: y = C + D*u
#pragma unroll
    for (int mi = 0; mi < 2; mi++) {
#pragma unroll
        for (int ni = 0; ni < 8; ni++) {
            int rm = m0 + wm + mi * 16 + gr;
            int ch = h0 + wn + ni * 8 + 2 * tg;
            float2 dv = *(const float2*)(D + ch);
            {
                size_t idx = (size_t)rm * H_ + ch;
                float2 uv = *(const float2*)(u + idx);
                float2 o;
                o.x = fmaf(dv.x, uv.x, c[mi][ni][0]);
                o.y = fmaf(dv.y, uv.y, c[mi][ni][1]);
                *(float2*)(y + idx) = o;
            }
            {
                size_t idx = (size_t)(rm + 8) * H_ + ch;
                float2 uv = *(const float2*)(u + idx);
                float2 o;
                o.x = fmaf(dv.x, uv.x, c[mi][ni][2]);
                o.y = fmaf(dv.y, uv.y, c[mi][ni][3]);
                *(float2*)(y + idx) = o;
            }
        }
    }
}

// ---------------------------------------------------------------------------
extern "C" void kernel_launch(void* const* d_in, const int* in_sizes, int n_in,
                              void* d_out, int out_size)
{
    const float* u     = (const float*)d_in[0];
    const float* lre   = (const float*)d_in[1];
    const float* lim   = (const float*)d_in[2];
    const float* Bre   = (const float*)d_in[3];
    const float* Bim   = (const float*)d_in[4];
    const float* Cre   = (const float*)d_in[5];
    const float* Cim   = (const float*)d_in[6];
    const float* D     = (const float*)d_in[7];
    const float* logdt = (const float*)d_in[8];
    float* y = (float*)d_out;

    prep_kernel<<<PC, H_>>>(lre, lim, Bre, Bim, Cre, Cim, logdt);
    gemm1_kernel<<<dim3(PC / BM, ML / BN), 256>>>(u);
    scan_kernel<<<dim3(P_, B_), 128>>>();
    gemm2_kernel<<<dim3(H_ / BN, ML / BM), 256>>>(u, D, y);
}

// round 17
// speedup vs baseline: 2.3557x; 1.0623x over previous
#include <cuda_runtime.h>
#include <math.h>
#include <stdint.h>

// Problem constants
#define L_  4096
#define H_  512
#define P_  256
#define B_  8
#define PC  512                 // 2*P (re plane then im plane)
#define ML  (B_ * L_)           // 32768

// GEMM tiling (tensor-core version)
#define BM  128
#define BN  128
#define BK  16
#define KST 20                  // [m][k] layout: padded k stride; 80B rows -> ldmatrix conflict-free
#define MST 136                 // [k][m] layout: padded m stride, conflict-free frag LDS + STS

#define ABYTES (BM * KST * 4)   // one buffer of As/Bs in gemm1 (10240 B)

// Scratch: Bu / xs buffer in (b, pc, l) layout, scanned in place. 67 MB.
__device__ float g_buf[(size_t)B_ * PC * L_];
__device__ float g_W1 [(size_t)PC * H_];   // (pc, h) row-major
__device__ float g_W2t[(size_t)H_ * PC];   // (h, pc) row-major
__device__ float g_lamre[P_], g_lamim[P_];

__device__ __forceinline__ float f2tf(float f) {
    uint32_t u;
    asm("cvt.rna.tf32.f32 %0, %1;" : "=r"(u) : "f"(f));
    return __uint_as_float(u);
}

__device__ __forceinline__ void mma_tf32(float* c, const uint32_t* a,
                                         uint32_t b0, uint32_t b1) {
    asm volatile(
        "mma.sync.aligned.m16n8k8.row.col.f32.tf32.tf32.f32 "
        "{%0,%1,%2,%3}, {%4,%5,%6,%7}, {%8,%9}, {%0,%1,%2,%3};"
        : "+f"(c[0]), "+f"(c[1]), "+f"(c[2]), "+f"(c[3])
        : "r"(a[0]), "r"(a[1]), "r"(a[2]), "r"(a[3]), "r"(b0), "r"(b1));
}

__device__ __forceinline__ void ldmx4(uint32_t& r0, uint32_t& r1,
                                      uint32_t& r2, uint32_t& r3, uint32_t saddr) {
    asm volatile("ldmatrix.sync.aligned.m8n8.x4.shared.b16 {%0,%1,%2,%3}, [%4];"
        : "=r"(r0), "=r"(r1), "=r"(r2), "=r"(r3) : "r"(saddr));
}

// ---------------------------------------------------------------------------
// K0: discretize + build fused weight matrices
// ---------------------------------------------------------------------------
__global__ void prep_kernel(const float* __restrict__ lre, const float* __restrict__ lim,
                            const float* __restrict__ Bre, const float* __restrict__ Bim,
                            const float* __restrict__ Cre, const float* __restrict__ Cim,
                            const float* __restrict__ logdt)
{
    int pc = blockIdx.x;            // 0..511
    int h  = threadIdx.x;           // 0..511
    int p  = pc & (P_ - 1);
    bool isim = pc >= P_;

    float lr = lre[p], li = lim[p];
    float dt = expf(logdt[p]);
    float e   = expf(lr * dt);
    float lbr = e * cosf(li * dt);
    float lbi = e * sinf(li * dt);
    float ar = lbr - 1.0f, ai = lbi;
    float den = lr * lr + li * li;
    float gr = (ar * lr + ai * li) / den;
    float gi = (ai * lr - ar * li) / den;
    float br = Bre[p * H_ + h], bi = Bim[p * H_ + h];
    g_W1[(size_t)pc * H_ + h]  = isim ? (gr * bi + gi * br) : (gr * br - gi * bi);
    g_W2t[(size_t)h * PC + pc] = isim ? (-2.0f * Cim[h * P_ + p]) : (2.0f * Cre[h * P_ + p]);

    if (h == 0 && !isim) { g_lamre[p] = lbr; g_lamim[p] = lbi; }
}

// ---------------------------------------------------------------------------
// K1 (tf32 + ldmatrix): Bu[pc, m] = sum_h W1[pc, h] * u[m, h]
//   A = W1 (pc, h); B = u (m, h); direct f4 copies into [row][k] KST layout.
//   Fragments fetched with ldmatrix.x4 (A: 1/mi/ks; B: 1 per ni-pair/ks).
//   Rows stride 80B -> 16B-groups 5r mod 8 all distinct: conflict-free.
// ---------------------------------------------------------------------------
__global__ __launch_bounds__(256, 2)
void gemm1_kernel(const float* __restrict__ u)
{
    __shared__ __align__(16) float As[2][BM][KST];   // [buf][pc][k]
    __shared__ __align__(16) float Bs[2][BN][KST];   // [buf][m][k]

    int r0 = blockIdx.x * BM;        // pc tile
    int c0 = blockIdx.y * BN;        // m tile (within one batch)
    int t  = threadIdx.x;
    int lane = t & 31, wid = t >> 5;
    int wm = (wid & 3) * 32, wn = (wid >> 2) * 64;
    int gr = lane >> 2, tg = lane & 3;

    int lrow = t >> 2;               // 0..63 (+64 via i)
    int lcol = (t & 3) * 4;

    const float* Ag = g_W1 + (size_t)r0 * H_;
    const float* Bg = u    + (size_t)c0 * H_;

    // ldmatrix per-lane address setup (byte offsets into a buffer)
    uint32_t sbA = (uint32_t)__cvta_generic_to_shared(&As[0][0][0]);
    uint32_t sbB = (uint32_t)__cvta_generic_to_shared(&Bs[0][0][0]);
    int tt = lane >> 3, rit = lane & 7;
    uint32_t offA[2], offB[4];
#pragma unroll
    for (int mi = 0; mi < 2; mi++) {
        int row = wm + mi * 16 + (tt & 1) * 8 + rit;
        int col = (tt >> 1) * 4;
        offA[mi] = sbA + (uint32_t)(row * KST + col) * 4;
    }
#pragma unroll
    for (int j = 0; j < 4; j++) {
        int nrow = wn + (2 * j + (tt >> 1)) * 8 + rit;
        int col = (tt & 1) * 4;
        offB[j] = sbB + (uint32_t)(nrow * KST + col) * 4;
    }

    float c[2][8][4];
#pragma unroll
    for (int mi = 0; mi < 2; mi++)
#pragma unroll
        for (int ni = 0; ni < 8; ni++)
#pragma unroll
            for (int q = 0; q < 4; q++) c[mi][ni][q] = 0.0f;

    // prologue: tile 0 -> buffer 0 (cvt to tf32 at store)
#pragma unroll
    for (int i = 0; i < 2; i++) {
        int row = lrow + i * 64;
        float4 va = *(const float4*)(Ag + (size_t)row * H_ + lcol);
        As[0][row][lcol + 0] = f2tf(va.x); As[0][row][lcol + 1] = f2tf(va.y);
        As[0][row][lcol + 2] = f2tf(va.z); As[0][row][lcol + 3] = f2tf(va.w);
        float4 vb = *(const float4*)(Bg + (size_t)row * H_ + lcol);
        Bs[0][row][lcol + 0] = f2tf(vb.x); Bs[0][row][lcol + 1] = f2tf(vb.y);
        Bs[0][row][lcol + 2] = f2tf(vb.z); Bs[0][row][lcol + 3] = f2tf(vb.w);
    }
    __syncthreads();

    const int NT = H_ / BK;          // 32
    for (int tI = 0; tI < NT; tI++) {
        int cur = tI & 1;
        uint32_t bufo = (uint32_t)cur * ABYTES;
        bool hn = (tI + 1 < NT);
        int k1 = (tI + 1) * BK;

        float4 ra[2], rb[2];
        if (hn) {
#pragma unroll
            for (int i = 0; i < 2; i++) {
                int row = lrow + i * 64;
                ra[i] = *(const float4*)(Ag + (size_t)row * H_ + k1 + lcol);
                rb[i] = *(const float4*)(Bg + (size_t)row * H_ + k1 + lcol);
            }
        }

#pragma unroll
        for (int ks = 0; ks < 2; ks++) {
            uint32_t kbo = (uint32_t)(ks * 8 * 4);   // k offset in bytes
            uint32_t a0[4], a1[4];
            ldmx4(a0[0], a0[1], a0[2], a0[3], offA[0] + bufo + kbo);
            ldmx4(a1[0], a1[1], a1[2], a1[3], offA[1] + bufo + kbo);
#pragma unroll
            for (int j = 0; j < 4; j++) {
                uint32_t b0, b1, b2, b3;
                ldmx4(b0, b1, b2, b3, offB[j] + bufo + kbo);
                mma_tf32(c[0][2 * j],     a0, b0, b1);
                mma_tf32(c[1][2 * j],     a1, b0, b1);
                mma_tf32(c[0][2 * j + 1], a0, b2, b3);
                mma_tf32(c[1][2 * j + 1], a1, b2, b3);
            }
        }

        if (hn) {
            int nx = cur ^ 1;
#pragma unroll
            for (int i = 0; i < 2; i++) {
                int row = lrow + i * 64;
                As[nx][row][lcol + 0] = f2tf(ra[i].x); As[nx][row][lcol + 1] = f2tf(ra[i].y);
                As[nx][row][lcol + 2] = f2tf(ra[i].z); As[nx][row][lcol + 3] = f2tf(ra[i].w);
                Bs[nx][row][lcol + 0] = f2tf(rb[i].x); Bs[nx][row][lcol + 1] = f2tf(rb[i].y);
                Bs[nx][row][lcol + 2] = f2tf(rb[i].z); Bs[nx][row][lcol + 3] = f2tf(rb[i].w);
            }
        }
        __syncthreads();
    }

    // epilogue: C[pc, m] -> g_buf[b*PC*L + pc*L + l]
    int b  = c0 >> 12;
    int l0 = c0 & (L_ - 1);
    float* out = g_buf + (size_t)b * PC * L_;
#pragma unroll
    for (int mi = 0; mi < 2; mi++) {
#pragma unroll
        for (int ni = 0; ni < 8; ni++) {
            int rp = r0 + wm + mi * 16 + gr;
            int cm = l0 + wn + ni * 8 + 2 * tg;
            float2 v0 = make_float2(c[mi][ni][0], c[mi][ni][1]);
            float2 v1 = make_float2(c[mi][ni][2], c[mi][ni][3]);
            *(float2*)(out + (size_t)rp * L_ + cm)       = v0;
            *(float2*)(out + (size_t)(rp + 8) * L_ + cm) = v1;
        }
    }
}

// ---------------------------------------------------------------------------
// K2: in-place scan along l for each (b, p):  x_k = lambda*x_{k-1} + Bu_k
// ---------------------------------------------------------------------------
__global__ __launch_bounds__(128)
void scan_kernel()
{
    int p = blockIdx.x;
    int b = blockIdx.y;
    float* re = g_buf + (size_t)b * PC * L_ + (size_t)p * L_;
    float* im = re + (size_t)P_ * L_;

    float lr = g_lamre[p], li = g_lamim[p];
    int t = threadIdx.x;

    float xr[32], xi[32];
    const float4* r4 = (const float4*)(re + t * 32);
    const float4* i4 = (const float4*)(im + t * 32);
#pragma unroll
    for (int i = 0; i < 8; i++) {
        float4 v = r4[i];
        xr[i * 4 + 0] = v.x; xr[i * 4 + 1] = v.y; xr[i * 4 + 2] = v.z; xr[i * 4 + 3] = v.w;
        float4 w = i4[i];
        xi[i * 4 + 0] = w.x; xi[i * 4 + 1] = w.y; xi[i * 4 + 2] = w.z; xi[i * 4 + 3] = w.w;
    }

    float ar = 0.0f, ai = 0.0f;
#pragma unroll
    for (int j = 0; j < 32; j++) {
        float nr = fmaf(lr, ar, fmaf(-li, ai, xr[j]));
        float ni = fmaf(lr, ai, fmaf( li, ar, xi[j]));
        ar = nr; ai = ni;
        xr[j] = ar; xi[j] = ai;
    }

    __shared__ float sr[128], si[128];
    sr[t] = ar; si[t] = ai;

    float wr = lr, wi = li;
#pragma unroll
    for (int q = 0; q < 5; q++) { float nr = wr * wr - wi * wi; wi = 2.0f * wr * wi; wr = nr; }

    __syncthreads();
    for (int d = 1; d < 128; d <<= 1) {
        float vr = 0.0f, vi = 0.0f;
        bool act = (t >= d);
        if (act) { vr = sr[t - d]; vi = si[t - d]; }
        __syncthreads();
        if (act) {
            float nr = fmaf(wr, vr, fmaf(-wi, vi, sr[t]));
            float ni = fmaf(wr, vi, fmaf( wi, vr, si[t]));
            sr[t] = nr; si[t] = ni;
        }
        __syncthreads();
        float nr = wr * wr - wi * wi; wi = 2.0f * wr * wi; wr = nr;
    }

    float Er = 0.0f, Ei = 0.0f;
    if (t > 0) { Er = sr[t - 1]; Ei = si[t - 1]; }

    float pr = lr, pi = li;
#pragma unroll
    for (int j = 0; j < 32; j++) {
        xr[j] = fmaf(pr, Er, fmaf(-pi, Ei, xr[j]));
        xi[j] = fmaf(pr, Ei, fmaf( pi, Er, xi[j]));
        float nr = pr * lr - pi * li;
        pi = pr * li + pi * lr;
        pr = nr;
    }

    float4* wr4 = (float4*)(re + t * 32);
    float4* wi4 = (float4*)(im + t * 32);
#pragma unroll
    for (int i = 0; i < 8; i++) {
        wr4[i] = make_float4(xr[i * 4 + 0], xr[i * 4 + 1], xr[i * 4 + 2], xr[i * 4 + 3]);
        wi4[i] = make_float4(xi[i * 4 + 0], xi[i * 4 + 1], xi[i * 4 + 2], xi[i * 4 + 3]);
    }
}

// ---------------------------------------------------------------------------
// K3 (tf32 + ldmatrix B): y[m, h] = sum_pc xs[pc, m] * W2[pc, h] + D[h]*u[m, h]
//   A tile [k][m] (MST=136): transpose STS contiguous (conflict-free), scalar
//   frag LDS (banks 8*tg+gr+d, distinct). B tile [h][k] KST via ldmatrix.x4.
// ---------------------------------------------------------------------------
__global__ __launch_bounds__(256, 2)
void gemm2_kernel(const float* __restrict__ u, const float* __restrict__ D,
                  float* __restrict__ y)
{
    __shared__ __align__(16) float As[2][BK][MST];   // [buf][k=pc][m]
    __shared__ __align__(16) float Bs[2][BN][KST];   // [buf][h][k=pc]

    int h0 = blockIdx.x * BN;
    int m0 = blockIdx.y * BM;
    int t  = threadIdx.x;
    int lane = t & 31, wid = t >> 5;
    int wm = (wid & 3) * 32, wn = (wid >> 2) * 64;
    int gr = lane >> 2, tg = lane & 3;

    int b  = m0 >> 12;
    int l0 = m0 & (L_ - 1);
    const float* Ag = g_buf + (size_t)b * PC * L_ + l0;   // row = pc, col = m (contig)
    const float* Bg = g_W2t + (size_t)h0 * PC;

    int a_mc = (t & 31) * 4;          // m offset 0..124 (per-warp full row)
    int lrow = t >> 2;                // B: h row 0..63 (+64)
    int lcol = (t & 3) * 4;           // B: k offset

    // ldmatrix setup for B
    uint32_t sbB = (uint32_t)__cvta_generic_to_shared(&Bs[0][0][0]);
    int tt = lane >> 3, rit = lane & 7;
    uint32_t offB[4];
#pragma unroll
    for (int j = 0; j < 4; j++) {
        int nrow = wn + (2 * j + (tt >> 1)) * 8 + rit;
        int col = (tt & 1) * 4;
        offB[j] = sbB + (uint32_t)(nrow * KST + col) * 4;
    }

    float c[2][8][4];
#pragma unroll
    for (int mi = 0; mi < 2; mi++)
#pragma unroll
        for (int ni = 0; ni < 8; ni++)
#pragma unroll
            for (int q = 0; q < 4; q++) c[mi][ni][q] = 0.0f;

    // prologue
#pragma unroll
    for (int i = 0; i < 2; i++) {
        int kr = wid + i * 8;
        float4 va = *(const float4*)(Ag + (size_t)kr * L_ + a_mc);
        float4 ca = make_float4(f2tf(va.x), f2tf(va.y), f2tf(va.z), f2tf(va.w));
        *(float4*)&As[0][kr][a_mc] = ca;
        int row = lrow + i * 64;
        float4 vb = *(const float4*)(Bg + (size_t)row * PC + lcol);
        Bs[0][row][lcol + 0] = f2tf(vb.x); Bs[0][row][lcol + 1] = f2tf(vb.y);
        Bs[0][row][lcol + 2] = f2tf(vb.z); Bs[0][row][lcol + 3] = f2tf(vb.w);
    }
    __syncthreads();

    const int NT = PC / BK;          // 32
    for (int tI = 0; tI < NT; tI++) {
        int cur = tI & 1;
        uint32_t bufo = (uint32_t)cur * (BN * KST * 4);
        bool hn = (tI + 1 < NT);
        int k1 = (tI + 1) * BK;

        float4 ra[2], rb[2];
        if (hn) {
#pragma unroll
            for (int i = 0; i < 2; i++) {
                int kr = wid + i * 8;
                ra[i] = *(const float4*)(Ag + (size_t)(k1 + kr) * L_ + a_mc);
                int row = lrow + i * 64;
                rb[i] = *(const float4*)(Bg + (size_t)row * PC + k1 + lcol);
            }
        }

#pragma unroll
        for (int ks = 0; ks < 2; ks++) {
            int kb = ks * 8;
            uint32_t kbo = (uint32_t)(kb * 4);
            uint32_t a[2][4];
#pragma unroll
            for (int mi = 0; mi < 2; mi++) {
                int r = wm + mi * 16 + gr;
                a[mi][0] = __float_as_uint(As[cur][kb + tg    ][r]);
                a[mi][1] = __float_as_uint(As[cur][kb + tg    ][r + 8]);
                a[mi][2] = __float_as_uint(As[cur][kb + tg + 4][r]);
                a[mi][3] = __float_as_uint(As[cur][kb + tg + 4][r + 8]);
            }
#pragma unroll
            for (int j = 0; j < 4; j++) {
                uint32_t b0, b1, b2, b3;
                ldmx4(b0, b1, b2, b3, offB[j] + bufo + kbo);
                mma_tf32(c[0][2 * j],     a[0], b0, b1);
                mma_tf32(c[1][2 * j],     a[1], b0, b1);
                mma_tf32(c[0][2 * j + 1], a[0], b2, b3);
                mma_tf32(c[1][2 * j + 1], a[1], b2, b3);
            }
        }

        if (hn) {
            int nx = cur ^ 1;
#pragma unroll
            for (int i = 0; i < 2; i++) {
                int kr = wid + i * 8;
                float4 ca = make_float4(f2tf(ra[i].x), f2tf(ra[i].y),
                                        f2tf(ra[i].z), f2tf(ra[i].w));
                *(float4*)&As[nx][kr][a_mc] = ca;
                int row = lrow + i * 64;
                Bs[nx][row][lcol + 0] = f2tf(rb[i].x); Bs[nx][row][lcol + 1] = f2tf(rb[i].y);
                Bs[nx][row][lcol + 2] = f2tf(rb[i].z); Bs[nx][row][lcol + 3] = f2tf(rb[i].w);
            }
        }
        __syncthreads();
    }

    // epilogue: y = C + D*u
#pragma unroll
    for (int mi = 0; mi < 2; mi++) {
#pragma unroll
        for (int ni = 0; ni < 8; ni++) {
            int rm = m0 + wm + mi * 16 + gr;
            int ch = h0 + wn + ni * 8 + 2 * tg;
            float2 dv = *(const float2*)(D + ch);
            {
                size_t idx = (size_t)rm * H_ + ch;
                float2 uv = *(const float2*)(u + idx);
                float2 o;
                o.x = fmaf(dv.x, uv.x, c[mi][ni][0]);
                o.y = fmaf(dv.y, uv.y, c[mi][ni][1]);
                *(float2*)(y + idx) = o;
            }
            {
                size_t idx = (size_t)(rm + 8) * H_ + ch;
                float2 uv = *(const float2*)(u + idx);
                float2 o;
                o.x = fmaf(dv.x, uv.x, c[mi][ni][2]);
                o.y = fmaf(dv.y, uv.y, c[mi][ni][3]);
                *(float2*)(y + idx) = o;
            }
        }
    }
}

// ---------------------------------------------------------------------------
extern "C" void kernel_launch(void* const* d_in, const int* in_sizes, int n_in,
                              void* d_out, int out_size)
{
    const float* u     = (const float*)d_in[0];
    const float* lre   = (const float*)d_in[1];
    const float* lim   = (const float*)d_in[2];
    const float* Bre   = (const float*)d_in[3];
    const float* Bim   = (const float*)d_in[4];
    const float* Cre   = (const float*)d_in[5];
    const float* Cim   = (const float*)d_in[6];
    const float* D     = (const float*)d_in[7];
    const float* logdt = (const float*)d_in[8];
    float* y = (float*)d_out;

    prep_kernel<<<PC, H_>>>(lre, lim, Bre, Bim, Cre, Cim, logdt);
    gemm1_kernel<<<dim3(PC / BM, ML / BN), 256>>>(u);
    scan_kernel<<<dim3(P_, B_), 128>>>();
    gemm2_kernel<<<dim3(H_ / BN, ML / BM), 256>>>(u, D, y);
}